// round 13
// baseline (speedup 1.0000x reference)
#include <cuda_runtime.h>
#include <cuda_fp16.h>
#include <math.h>
#include <stdint.h>

// ---------------- problem constants ----------------
#define NB1 8192
#define NB2 8192
#define ND  128

// ---------------- phase A tiling ----------------
#define BM 128
#define BN 64
#define SPLITC 16
#define COLS_PER_CTA (NB2 / SPLITC)          // 512
#define OUTER (COLS_PER_CTA / (2 * BN))      // 4 iterations x 128 cols

// u8 quantization: u = sat_u8(round(qn2 - dot*2/QSTEP)), qn2 = (n2-QLO)/QSTEP
#define QLO   (-64.0f)
#define QSTEP 1.5f
#define QINV  (1.0f / QSTEP)
#define MQ2   (-2.0f * QINV)
#define THR_STEPS 3          // 4.5 decoded margin (fp32 acc; need >= 2.06)

// smem map: Ah 32KB | Bh ring 4 x 16KB | qn2 2KB
#define SMEM_A 0
#define SMEM_B 32768
#define BSTAGE 16384
#define SMEM_N2 (SMEM_B + 4 * BSTAGE)        // 98304
#define SMEM_BYTES (SMEM_N2 + 2048)          // 100352 (2 CTAs/SM)

#define SW128(o) ((o) ^ (((o) >> 3) & 0x70))

// ---------------- scratch globals ----------------
__device__ __align__(16) float  g_n1[NB1];
__device__ __align__(16) float  g_n2[NB2];
__device__ __align__(16) float  g_qn2[NB2];                      // (n2 - QLO) * QINV
__device__ __align__(16) __half g_Ah[NB1 * ND];
__device__ __align__(16) __half g_Bh[NB2 * ND];
__device__ __align__(16) uint8_t g_vbuf[(size_t)NB1 * NB2];      // 64MB u8 screen values
__device__ __align__(16) uint8_t g_rmin[NB1 * SPLITC * 2];       // per (row, split, colwarp) min

// ---------------- PTX helpers (portable sm_80-level only) ----------------
__device__ __forceinline__ uint32_t smem_u32(const void* p) {
    uint32_t a;
    asm("{ .reg .u64 t; cvta.to.shared.u64 t, %1; cvt.u32.u64 %0, t; }" : "=r"(a) : "l"(p));
    return a;
}
#define CP_ASYNC16(dst, src) \
    asm volatile("cp.async.cg.shared.global [%0], [%1], 16;" :: "r"(dst), "l"(src) : "memory")
#define CP_COMMIT() asm volatile("cp.async.commit_group;" ::: "memory")
#define CP_WAIT0()  asm volatile("cp.async.wait_group 0;" ::: "memory")

#define LDMATRIX_X4(r0, r1, r2, r3, addr) \
    asm volatile("ldmatrix.sync.aligned.m8n8.x4.shared.b16 {%0,%1,%2,%3}, [%4];" \
        : "=r"(r0), "=r"(r1), "=r"(r2), "=r"(r3) : "r"(addr))

#define MMA16816(acc, a, b0v, b1v) \
    asm volatile("mma.sync.aligned.m16n8k16.row.col.f32.f16.f16.f32 " \
        "{%0,%1,%2,%3}, {%4,%5,%6,%7}, {%8,%9}, {%0,%1,%2,%3};" \
        : "+f"((acc)[0]), "+f"((acc)[1]), "+f"((acc)[2]), "+f"((acc)[3]) \
        : "r"((a)[0]), "r"((a)[1]), "r"((a)[2]), "r"((a)[3]), "r"(b0v), "r"(b1v))

// pack 4 s32 -> 4 sat-u8 bytes (little-endian v0..v3)
__device__ __forceinline__ uint32_t pack4(int a0, int a1, int a2, int a3) {
    uint32_t r;
    asm("{ .reg .u32 t;\n\t"
        "cvt.pack.sat.u8.s32.b32 t, %4, %3, 0;\n\t"
        "cvt.pack.sat.u8.s32.b32 %0, %2, %1, t;\n\t}"
        : "=r"(r) : "r"(a0), "r"(a1), "r"(a2), "r"(a3));
    return r;
}

// ---------------------------------------------------------------------------
// Kernel 0: fp16 hi conversion + squared norms (+ prescaled qn2). Warp/row.
// ---------------------------------------------------------------------------
__global__ void prep_kernel(const float* __restrict__ d1,
                            const float* __restrict__ d2) {
    int warp = (blockIdx.x * blockDim.x + threadIdx.x) >> 5;
    int lane = threadIdx.x & 31;
    if (warp >= NB1 + NB2) return;
    bool isB = (warp >= NB1);
    int row = isB ? warp - NB1 : warp;
    const float* src = (isB ? d2 : d1) + (size_t)row * ND;
    float4 v = ((const float4*)src)[lane];

    float s = v.x * v.x + v.y * v.y + v.z * v.z + v.w * v.w;
    #pragma unroll
    for (int o = 16; o; o >>= 1) s += __shfl_xor_sync(0xffffffffu, s, o);
    if (lane == 0) {
        if (isB) { g_n2[row] = s; g_qn2[row] = (s - QLO) * QINV; }
        else     g_n1[row] = s;
    }

    __half2 h01 = __halves2half2(__float2half_rn(v.x), __float2half_rn(v.y));
    __half2 h23 = __halves2half2(__float2half_rn(v.z), __float2half_rn(v.w));
    uint2 hp = make_uint2(*(uint32_t*)&h01, *(uint32_t*)&h23);
    ((uint2*)(isB ? g_Bh : g_Ah))[(size_t)row * 32 + lane] = hp;
}

// ---------------------------------------------------------------------------
// smem loaders (SW128-swizzled K-major hi tiles)
// ---------------------------------------------------------------------------
__device__ __forceinline__ void load_a_panel(uint32_t dstbase, int row0, int tid) {
    #pragma unroll
    for (int g = 0; g < 8; g++) {
        int idx = g * 256 + tid;
        int chunk = idx >> 10;
        int rem   = idx & 1023;
        int row   = rem >> 3;
        int gi    = rem & 7;
        const __half* src = g_Ah + (size_t)(row0 + row) * ND + chunk * 64 + gi * 8;
        CP_ASYNC16(dstbase + chunk * 16384 + SW128(row * 128 + gi * 16), src);
    }
}
__device__ __forceinline__ void load_b_stage(uint32_t dstbase, int col0, int tid) {
    #pragma unroll
    for (int g = 0; g < 4; g++) {
        int idx = g * 256 + tid;
        int chunk = idx >> 9;
        int rem   = idx & 511;
        int row   = rem >> 3;
        int gi    = rem & 7;
        const __half* src = g_Bh + (size_t)(col0 + row) * ND + chunk * 64 + gi * 8;
        CP_ASYNC16(dstbase + chunk * 8192 + SW128(row * 128 + gi * 16), src);
    }
}

// ---------------------------------------------------------------------------
// Kernel 1 (screen): hi-only mma.sync GEMM (fp32 acc). Slim epilogue:
// u8 = sat_u8(round(fma(dot, -2/QSTEP, qn2))) via FFMA+F2I+cvt.pack.sat,
// one STG.128 per (m,ch), register running byte-min -> g_rmin at the end.
//   byte p (within the 128B iter-chunk) = w1*64 + l3*16 + sub*8 + n*2 + c
//   column j (within the chunk)         = sub*64 + w1*32 + n*8 + l3*2 + c
// ---------------------------------------------------------------------------
__global__ void __launch_bounds__(256, 2)
screen_kernel() {
    extern __shared__ char smem[];
    const uint32_t sbase = smem_u32(smem);
    const int tid  = threadIdx.x;
    const int lane = tid & 31;
    const int warp = tid >> 5;
    const int wrow = (warp >> 1) * 32;
    const int wcol = (warp & 1) * 32;
    const int rowBase = blockIdx.x * BM;
    const int split   = blockIdx.y;
    const int colBase = split * COLS_PER_CTA;

    const int a_rl   = lane & 15;
    const int a_koff = (lane >> 4) * 8;
    const int b_nl   = (lane & 7) + (lane >> 4) * 8;
    const int b_koff = ((lane >> 3) & 1) * 8;

    // ---- prologue: A panel + qn2 + stages 0,1 ----
    load_a_panel(sbase + SMEM_A, rowBase, tid);
    if (tid < 128)
        CP_ASYNC16(sbase + SMEM_N2 + tid * 16, g_qn2 + colBase + tid * 4);
    load_b_stage(sbase + SMEM_B + 0 * BSTAGE, colBase + 0 * BN, tid);
    CP_COMMIT();
    load_b_stage(sbase + SMEM_B + 1 * BSTAGE, colBase + 1 * BN, tid);
    CP_COMMIT();

    const float* qn2s = (const float*)(smem + SMEM_N2);

    uint32_t rmin[2][2] = {{0xFFFFFFFFu, 0xFFFFFFFFu}, {0xFFFFFFFFu, 0xFFFFFFFFu}};

    for (int it = 0; it < OUTER; it++) {
        CP_WAIT0();
        __syncthreads();

        if (it + 1 < OUTER) {
            load_b_stage(sbase + SMEM_B + (((it + 1) * 2) & 3) * BSTAGE,
                         colBase + (it + 1) * 2 * BN, tid);
            CP_COMMIT();
            load_b_stage(sbase + SMEM_B + (((it + 1) * 2 + 1) & 3) * BSTAGE,
                         colBase + ((it + 1) * 2 + 1) * BN, tid);
            CP_COMMIT();
        }

        const uint32_t abase = sbase + SMEM_A;
        const uint32_t bbase0 = sbase + SMEM_B + ((it * 2) & 3) * BSTAGE;
        const uint32_t bbase1 = sbase + SMEM_B + ((it * 2 + 1) & 3) * BSTAGE;

        float acc[2][2][4][4];     // [m][subtile][npair][c]
        #pragma unroll
        for (int m = 0; m < 2; m++)
            #pragma unroll
            for (int sub = 0; sub < 2; sub++)
                #pragma unroll
                for (int n = 0; n < 4; n++)
                    #pragma unroll
                    for (int c = 0; c < 4; c++) acc[m][sub][n][c] = 0.0f;

        #pragma unroll
        for (int ks = 0; ks < 8; ks++) {
            uint32_t aH[2][4];
            #pragma unroll
            for (int m = 0; m < 2; m++) {
                int row = wrow + m * 16 + a_rl;
                int kb  = ks * 16 + a_koff;
                uint32_t addr = abase + (kb >> 6) * 16384 + row * 128 +
                                (((kb & 63) * 2) ^ ((row & 7) << 4));
                LDMATRIX_X4(aH[m][0], aH[m][1], aH[m][2], aH[m][3], addr);
            }
            #pragma unroll
            for (int sub = 0; sub < 2; sub++) {
                const uint32_t bbase = sub ? bbase1 : bbase0;
                uint32_t bH[2][4];
                #pragma unroll
                for (int pr = 0; pr < 2; pr++) {
                    int nrow = wcol + pr * 16 + b_nl;
                    int kb   = ks * 16 + b_koff;
                    uint32_t addr = bbase + (kb >> 6) * 8192 + nrow * 128 +
                                    (((kb & 63) * 2) ^ ((nrow & 7) << 4));
                    LDMATRIX_X4(bH[pr][0], bH[pr][1], bH[pr][2], bH[pr][3], addr);
                }
                #pragma unroll
                for (int m = 0; m < 2; m++) {
                    MMA16816(acc[m][sub][0], aH[m], bH[0][0], bH[0][1]);
                    MMA16816(acc[m][sub][1], aH[m], bH[0][2], bH[0][3]);
                    MMA16816(acc[m][sub][2], aH[m], bH[1][0], bH[1][1]);
                    MMA16816(acc[m][sub][3], aH[m], bH[1][2], bH[1][3]);
                }
            }
        }

        // ---- epilogue: FFMA + F2I + sat-pack, running min, STG.128 per (m,ch)
        float qn2v[2][8];
        #pragma unroll
        for (int sub = 0; sub < 2; sub++) {
            const int cloc = it * 128 + sub * 64 + wcol;
            #pragma unroll
            for (int n = 0; n < 4; n++) {
                qn2v[sub][n * 2]     = qn2s[cloc + n * 8 + (lane & 3) * 2];
                qn2v[sub][n * 2 + 1] = qn2s[cloc + n * 8 + (lane & 3) * 2 + 1];
            }
        }
        #pragma unroll
        for (int m = 0; m < 2; m++) {
            #pragma unroll
            for (int ch = 0; ch < 2; ch++) {
                uint32_t w[4];
                #pragma unroll
                for (int sub = 0; sub < 2; sub++) {
                    #pragma unroll
                    for (int np = 0; np < 2; np++) {
                        int n0 = np * 2, n1 = np * 2 + 1;
                        int i0 = __float2int_rn(fmaf(acc[m][sub][n0][ch * 2],
                                                     MQ2, qn2v[sub][n0 * 2]));
                        int i1 = __float2int_rn(fmaf(acc[m][sub][n0][ch * 2 + 1],
                                                     MQ2, qn2v[sub][n0 * 2 + 1]));
                        int i2 = __float2int_rn(fmaf(acc[m][sub][n1][ch * 2],
                                                     MQ2, qn2v[sub][n1 * 2]));
                        int i3 = __float2int_rn(fmaf(acc[m][sub][n1][ch * 2 + 1],
                                                     MQ2, qn2v[sub][n1 * 2 + 1]));
                        w[sub * 2 + np] = pack4(i0, i1, i2, i3);
                    }
                }
                rmin[m][ch] = __vminu4(rmin[m][ch],
                              __vminu4(__vminu4(w[0], w[1]), __vminu4(w[2], w[3])));
                int grow = rowBase + wrow + m * 16 + ch * 8 + (lane >> 2);
                size_t p = (size_t)grow * NB2 + split * 512 + it * 128 +
                           (warp & 1) * 64 + (lane & 3) * 16;
                *(uint4*)(g_vbuf + p) = make_uint4(w[0], w[1], w[2], w[3]);
            }
        }
    }

    // ---- final: quad-reduce running mins, one byte store per row-slot ----
    #pragma unroll
    for (int m = 0; m < 2; m++)
        #pragma unroll
        for (int ch = 0; ch < 2; ch++) {
            uint32_t v = rmin[m][ch];
            v = __vminu4(v, __shfl_xor_sync(0xffffffffu, v, 1));
            v = __vminu4(v, __shfl_xor_sync(0xffffffffu, v, 2));
            uint32_t b = min(min(v & 255u, (v >> 8) & 255u),
                             min((v >> 16) & 255u, (v >> 24) & 255u));
            if ((lane & 3) == 0) {
                int grow = rowBase + wrow + m * 16 + ch * 8 + (lane >> 2);
                g_rmin[(grow * SPLITC + split) * 2 + (warp & 1)] = (uint8_t)b;
            }
        }
}

// ---------------------------------------------------------------------------
// Kernel 2 (scan): warp per row. Threshold from g_rmin (32 bytes), one sweep:
// candidates u <= umin + THR_STEPS, exact fp32 rescore, first-index tie-break.
// ---------------------------------------------------------------------------
__global__ void scan_kernel(const float* __restrict__ d1,
                            const float* __restrict__ d2,
                            float* __restrict__ out) {
    int warp = (blockIdx.x * blockDim.x + threadIdx.x) >> 5;
    int lane = threadIdx.x & 31;
    if (warp >= NB1) return;
    const int row = warp;
    const uint4* vrow = (const uint4*)(g_vbuf + (size_t)row * NB2);  // 512 uint4

    // ---- threshold from precomputed per-split mins (32 bytes) ----
    uint32_t mn = 0xFFFFFFFFu;
    if (lane < 8)
        mn = ((const uint32_t*)(g_rmin + row * SPLITC * 2))[lane];
    #pragma unroll
    for (int o = 4; o; o >>= 1)
        mn = __vminu4(mn, __shfl_xor_sync(0xffffffffu, mn, o));
    mn = __shfl_sync(0xffffffffu, mn, 0);
    uint32_t umin = min(min(mn & 255u, (mn >> 8) & 255u),
                        min((mn >> 16) & 255u, (mn >> 24) & 255u));
    uint32_t uthr = min(umin + THR_STEPS, 255u);
    const uint32_t thr4 = uthr * 0x01010101u;

    // ---- single sweep: candidates + exact rescore ----
    float4 a4 = ((const float4*)(d1 + (size_t)row * ND))[lane];
    float n1r = g_n1[row];
    float bv = 3.4e38f;
    int   bj = 0x7fffffff;

    for (int it = 0; it < 16; it++) {
        uint4 q = vrow[it * 32 + lane];
        bool f = (__vcmpleu4(q.x, thr4) | __vcmpleu4(q.y, thr4) |
                  __vcmpleu4(q.z, thr4) | __vcmpleu4(q.w, thr4)) != 0u;
        unsigned bm = __ballot_sync(0xffffffffu, f);
        while (bm) {
            int src = __ffs(bm) - 1;
            bm &= bm - 1;
            uint32_t qs[4];
            qs[0] = __shfl_sync(0xffffffffu, q.x, src);
            qs[1] = __shfl_sync(0xffffffffu, q.y, src);
            qs[2] = __shfl_sync(0xffffffffu, q.z, src);
            qs[3] = __shfl_sync(0xffffffffu, q.w, src);
            #pragma unroll
            for (int wj = 0; wj < 4; wj++) {
                uint32_t cm = __vcmpleu4(qs[wj], thr4);
                while (cm) {
                    int bit = __ffs(cm) - 1;
                    cm &= ~(0xFFu << (bit & ~7));
                    int k = wj * 4 + (bit >> 3);
                    int p = (it * 32 + src) * 16 + k;
                    // inverse permutation: byte index p -> column j
                    int r7  = p & 127;
                    int w1  = r7 >> 6;
                    int l3  = (r7 >> 4) & 3;
                    int sub = (r7 >> 3) & 1;
                    int n   = (r7 >> 1) & 3;
                    int c   = r7 & 1;
                    int j = (p & ~127) + sub * 64 + w1 * 32 + n * 8 + l3 * 2 + c;
                    float4 b4 = ((const float4*)(d2 + (size_t)j * ND))[lane];
                    float d = a4.x * b4.x + a4.y * b4.y + a4.z * b4.z + a4.w * b4.w;
                    #pragma unroll
                    for (int o = 16; o; o >>= 1)
                        d += __shfl_xor_sync(0xffffffffu, d, o);
                    float v = n1r + g_n2[j] - 2.0f * d;
                    if (v < bv || (v == bv && j < bj)) { bv = v; bj = j; }
                }
            }
        }
    }

    if (lane == 0) {
        out[row] = sqrtf(fmaxf(bv, 0.0f));
        out[NB1 + 2 * row]     = (float)row;
        out[NB1 + 2 * row + 1] = (float)bj;
    }
}

// ---------------------------------------------------------------------------
extern "C" void kernel_launch(void* const* d_in, const int* in_sizes, int n_in,
                              void* d_out, int out_size) {
    const float* d1 = (const float*)d_in[0];
    const float* d2 = (const float*)d_in[1];
    float* out = (float*)d_out;

    cudaFuncSetAttribute(screen_kernel,
                         cudaFuncAttributeMaxDynamicSharedMemorySize, SMEM_BYTES);

    prep_kernel<<<(NB1 + NB2) / 8, 256>>>(d1, d2);
    screen_kernel<<<dim3(NB1 / BM, SPLITC), 256, SMEM_BYTES>>>();
    scan_kernel<<<NB1 / 8, 256>>>(d1, d2, out);
}

// round 15
// speedup vs baseline: 1.1941x; 1.1941x over previous
#include <cuda_runtime.h>
#include <cuda_fp16.h>
#include <math.h>
#include <stdint.h>

// ---------------- problem constants ----------------
#define NB1 8192
#define NB2 8192
#define ND  128

// ---------------- phase A tiling ----------------
#define BM 128
#define BN 64
#define SPLITC 32
#define COLS_PER_CTA (NB2 / SPLITC)          // 256
#define OUTER (COLS_PER_CTA / (2 * BN))      // 2 iterations x 128 cols

// u8 quantization of screen values: u = clamp(round((v - QLO) / QSTEP))
#define QLO   (-64.0f)
#define QSTEP 1.5f
#define QINV  (1.0f / QSTEP)
#define THR_STEPS 3          // 4.5 decoded margin (need >= 2.06)

// smem map: Ah 32KB | Bh ring 4 x 16KB | n2 1KB
#define SMEM_A 0
#define SMEM_B 32768
#define BSTAGE 16384
#define SMEM_N2 (SMEM_B + 4 * BSTAGE)        // 98304
#define SMEM_BYTES (SMEM_N2 + 1024)          // 99328 (2 CTAs/SM)

#define SW128(o) ((o) ^ (((o) >> 3) & 0x70))

// ---------------- scratch globals ----------------
__device__ __align__(16) float  g_n1[NB1];
__device__ __align__(16) float  g_n2[NB2];
__device__ __align__(16) __half g_Ah[NB1 * ND];
__device__ __align__(16) __half g_Bh[NB2 * ND];
__device__ __align__(16) uint8_t g_vbuf[(size_t)NB1 * NB2];      // 64MB u8 screen values
__device__ __align__(16) uint8_t g_rmin[NB1 * SPLITC * 2];       // per (row, split, colwarp) min

// ---------------- PTX helpers (portable sm_80-level only) ----------------
__device__ __forceinline__ uint32_t smem_u32(const void* p) {
    uint32_t a;
    asm("{ .reg .u64 t; cvta.to.shared.u64 t, %1; cvt.u32.u64 %0, t; }" : "=r"(a) : "l"(p));
    return a;
}
#define CP_ASYNC16(dst, src) \
    asm volatile("cp.async.cg.shared.global [%0], [%1], 16;" :: "r"(dst), "l"(src) : "memory")
#define CP_COMMIT() asm volatile("cp.async.commit_group;" ::: "memory")
#define CP_WAIT0()  asm volatile("cp.async.wait_group 0;" ::: "memory")

#define LDMATRIX_X4(r0, r1, r2, r3, addr) \
    asm volatile("ldmatrix.sync.aligned.m8n8.x4.shared.b16 {%0,%1,%2,%3}, [%4];" \
        : "=r"(r0), "=r"(r1), "=r"(r2), "=r"(r3) : "r"(addr))

#define MMA16816(acc, a, b0v, b1v) \
    asm volatile("mma.sync.aligned.m16n8k16.row.col.f32.f16.f16.f32 " \
        "{%0,%1,%2,%3}, {%4,%5,%6,%7}, {%8,%9}, {%0,%1,%2,%3};" \
        : "+f"((acc)[0]), "+f"((acc)[1]), "+f"((acc)[2]), "+f"((acc)[3]) \
        : "r"((a)[0]), "r"((a)[1]), "r"((a)[2]), "r"((a)[3]), "r"(b0v), "r"(b1v))

__device__ __forceinline__ uint32_t quant4(float v0, float v1, float v2, float v3) {
    int u0 = __float2int_rn((v0 - QLO) * QINV);
    int u1 = __float2int_rn((v1 - QLO) * QINV);
    int u2 = __float2int_rn((v2 - QLO) * QINV);
    int u3 = __float2int_rn((v3 - QLO) * QINV);
    u0 = min(max(u0, 0), 255); u1 = min(max(u1, 0), 255);
    u2 = min(max(u2, 0), 255); u3 = min(max(u3, 0), 255);
    return (uint32_t)u0 | ((uint32_t)u1 << 8) | ((uint32_t)u2 << 16) | ((uint32_t)u3 << 24);
}

// ---------------------------------------------------------------------------
// Kernel 0: fp16 hi conversion + squared norms. One warp per row.
// ---------------------------------------------------------------------------
__global__ void prep_kernel(const float* __restrict__ d1,
                            const float* __restrict__ d2) {
    int warp = (blockIdx.x * blockDim.x + threadIdx.x) >> 5;
    int lane = threadIdx.x & 31;
    if (warp >= NB1 + NB2) return;
    bool isB = (warp >= NB1);
    int row = isB ? warp - NB1 : warp;
    const float* src = (isB ? d2 : d1) + (size_t)row * ND;
    float4 v = ((const float4*)src)[lane];

    float s = v.x * v.x + v.y * v.y + v.z * v.z + v.w * v.w;
    #pragma unroll
    for (int o = 16; o; o >>= 1) s += __shfl_xor_sync(0xffffffffu, s, o);
    if (lane == 0) {
        if (isB) g_n2[row] = s;
        else     g_n1[row] = s;
    }

    __half2 h01 = __halves2half2(__float2half_rn(v.x), __float2half_rn(v.y));
    __half2 h23 = __halves2half2(__float2half_rn(v.z), __float2half_rn(v.w));
    uint2 hp = make_uint2(*(uint32_t*)&h01, *(uint32_t*)&h23);
    ((uint2*)(isB ? g_Bh : g_Ah))[(size_t)row * 32 + lane] = hp;
}

// ---------------------------------------------------------------------------
// smem loaders (SW128-swizzled K-major hi tiles)
// ---------------------------------------------------------------------------
__device__ __forceinline__ void load_a_panel(uint32_t dstbase, int row0, int tid) {
    #pragma unroll
    for (int g = 0; g < 8; g++) {
        int idx = g * 256 + tid;
        int chunk = idx >> 10;
        int rem   = idx & 1023;
        int row   = rem >> 3;
        int gi    = rem & 7;
        const __half* src = g_Ah + (size_t)(row0 + row) * ND + chunk * 64 + gi * 8;
        CP_ASYNC16(dstbase + chunk * 16384 + SW128(row * 128 + gi * 16), src);
    }
}
__device__ __forceinline__ void load_b_stage(uint32_t dstbase, int col0, int tid) {
    #pragma unroll
    for (int g = 0; g < 4; g++) {
        int idx = g * 256 + tid;
        int chunk = idx >> 9;
        int rem   = idx & 511;
        int row   = rem >> 3;
        int gi    = rem & 7;
        const __half* src = g_Bh + (size_t)(col0 + row) * ND + chunk * 64 + gi * 8;
        CP_ASYNC16(dstbase + chunk * 8192 + SW128(row * 128 + gi * 16), src);
    }
}

// ---------------------------------------------------------------------------
// Kernel 1 (screen): hi-only mma.sync GEMM; epilogue quantizes v = n2 - 2*dot
// to u8, stores PERMUTED (one STG.128 per (m,ch)), and keeps a register
// running byte-min per (m,ch) row-slot; quad-reduced min -> g_rmin at the end.
//   byte p (within the 128B iter-chunk) = w1*64 + l3*16 + sub*8 + n*2 + c
//   column j (within the chunk)         = sub*64 + w1*32 + n*8 + l3*2 + c
// ---------------------------------------------------------------------------
__global__ void __launch_bounds__(256, 2)
screen_kernel() {
    extern __shared__ char smem[];
    const uint32_t sbase = smem_u32(smem);
    const int tid  = threadIdx.x;
    const int lane = tid & 31;
    const int warp = tid >> 5;
    const int wrow = (warp >> 1) * 32;
    const int wcol = (warp & 1) * 32;
    const int rowBase = blockIdx.x * BM;
    const int split   = blockIdx.y;
    const int colBase = split * COLS_PER_CTA;

    const int a_rl   = lane & 15;
    const int a_koff = (lane >> 4) * 8;
    const int b_nl   = (lane & 7) + (lane >> 4) * 8;
    const int b_koff = ((lane >> 3) & 1) * 8;

    // ---- prologue: A panel + n2 + stages 0,1 ----
    load_a_panel(sbase + SMEM_A, rowBase, tid);
    if (tid < 64)
        CP_ASYNC16(sbase + SMEM_N2 + tid * 16, g_n2 + colBase + tid * 4);
    load_b_stage(sbase + SMEM_B + 0 * BSTAGE, colBase + 0 * BN, tid);
    CP_COMMIT();
    load_b_stage(sbase + SMEM_B + 1 * BSTAGE, colBase + 1 * BN, tid);
    CP_COMMIT();

    const float* n2s = (const float*)(smem + SMEM_N2);

    uint32_t rmin[2][2] = {{0xFFFFFFFFu, 0xFFFFFFFFu}, {0xFFFFFFFFu, 0xFFFFFFFFu}};

    for (int it = 0; it < OUTER; it++) {
        CP_WAIT0();
        __syncthreads();

        if (it + 1 < OUTER) {
            load_b_stage(sbase + SMEM_B + (((it + 1) * 2) & 3) * BSTAGE,
                         colBase + (it + 1) * 2 * BN, tid);
            CP_COMMIT();
            load_b_stage(sbase + SMEM_B + (((it + 1) * 2 + 1) & 3) * BSTAGE,
                         colBase + ((it + 1) * 2 + 1) * BN, tid);
            CP_COMMIT();
        }

        const uint32_t abase = sbase + SMEM_A;
        const uint32_t bbase0 = sbase + SMEM_B + ((it * 2) & 3) * BSTAGE;
        const uint32_t bbase1 = sbase + SMEM_B + ((it * 2 + 1) & 3) * BSTAGE;

        float acc[2][2][4][4];     // [m][subtile][npair][c]
        #pragma unroll
        for (int m = 0; m < 2; m++)
            #pragma unroll
            for (int sub = 0; sub < 2; sub++)
                #pragma unroll
                for (int n = 0; n < 4; n++)
                    #pragma unroll
                    for (int c = 0; c < 4; c++) acc[m][sub][n][c] = 0.0f;

        #pragma unroll
        for (int ks = 0; ks < 8; ks++) {
            uint32_t aH[2][4];
            #pragma unroll
            for (int m = 0; m < 2; m++) {
                int row = wrow + m * 16 + a_rl;
                int kb  = ks * 16 + a_koff;
                uint32_t addr = abase + (kb >> 6) * 16384 + row * 128 +
                                (((kb & 63) * 2) ^ ((row & 7) << 4));
                LDMATRIX_X4(aH[m][0], aH[m][1], aH[m][2], aH[m][3], addr);
            }
            #pragma unroll
            for (int sub = 0; sub < 2; sub++) {
                const uint32_t bbase = sub ? bbase1 : bbase0;
                uint32_t bH[2][4];
                #pragma unroll
                for (int pr = 0; pr < 2; pr++) {
                    int nrow = wcol + pr * 16 + b_nl;
                    int kb   = ks * 16 + b_koff;
                    uint32_t addr = bbase + (kb >> 6) * 8192 + nrow * 128 +
                                    (((kb & 63) * 2) ^ ((nrow & 7) << 4));
                    LDMATRIX_X4(bH[pr][0], bH[pr][1], bH[pr][2], bH[pr][3], addr);
                }
                #pragma unroll
                for (int m = 0; m < 2; m++) {
                    MMA16816(acc[m][sub][0], aH[m], bH[0][0], bH[0][1]);
                    MMA16816(acc[m][sub][1], aH[m], bH[0][2], bH[0][3]);
                    MMA16816(acc[m][sub][2], aH[m], bH[1][0], bH[1][1]);
                    MMA16816(acc[m][sub][3], aH[m], bH[1][2], bH[1][3]);
                }
            }
        }

        // ---- epilogue: quantize to u8, running min, one STG.128 per (m,ch) ----
        float n2v[2][8];
        #pragma unroll
        for (int sub = 0; sub < 2; sub++) {
            const int cloc = it * 128 + sub * 64 + wcol;
            #pragma unroll
            for (int n = 0; n < 4; n++) {
                n2v[sub][n * 2]     = n2s[cloc + n * 8 + (lane & 3) * 2];
                n2v[sub][n * 2 + 1] = n2s[cloc + n * 8 + (lane & 3) * 2 + 1];
            }
        }
        #pragma unroll
        for (int m = 0; m < 2; m++) {
            #pragma unroll
            for (int ch = 0; ch < 2; ch++) {
                uint32_t w[4];
                #pragma unroll
                for (int sub = 0; sub < 2; sub++) {
                    #pragma unroll
                    for (int np = 0; np < 2; np++) {
                        int n0 = np * 2, n1 = np * 2 + 1;
                        w[sub * 2 + np] = quant4(
                            n2v[sub][n0 * 2]     - 2.0f * acc[m][sub][n0][ch * 2],
                            n2v[sub][n0 * 2 + 1] - 2.0f * acc[m][sub][n0][ch * 2 + 1],
                            n2v[sub][n1 * 2]     - 2.0f * acc[m][sub][n1][ch * 2],
                            n2v[sub][n1 * 2 + 1] - 2.0f * acc[m][sub][n1][ch * 2 + 1]);
                    }
                }
                rmin[m][ch] = __vminu4(rmin[m][ch],
                              __vminu4(__vminu4(w[0], w[1]), __vminu4(w[2], w[3])));
                int grow = rowBase + wrow + m * 16 + ch * 8 + (lane >> 2);
                size_t p = (size_t)grow * NB2 + colBase + it * 128 +
                           (warp & 1) * 64 + (lane & 3) * 16;
                *(uint4*)(g_vbuf + p) = make_uint4(w[0], w[1], w[2], w[3]);
            }
        }
    }

    // ---- final: quad-reduce running mins, one byte store per row-slot ----
    #pragma unroll
    for (int m = 0; m < 2; m++)
        #pragma unroll
        for (int ch = 0; ch < 2; ch++) {
            uint32_t v = rmin[m][ch];
            v = __vminu4(v, __shfl_xor_sync(0xffffffffu, v, 1));
            v = __vminu4(v, __shfl_xor_sync(0xffffffffu, v, 2));
            uint32_t b = min(min(v & 255u, (v >> 8) & 255u),
                             min((v >> 16) & 255u, (v >> 24) & 255u));
            if ((lane & 3) == 0) {
                int grow = rowBase + wrow + m * 16 + ch * 8 + (lane >> 2);
                g_rmin[(grow * SPLITC + split) * 2 + (warp & 1)] = (uint8_t)b;
            }
        }
}

// ---------------------------------------------------------------------------
// Kernel 2 (scan): warp per row. Threshold from g_rmin (64 bytes), one sweep:
// candidates u <= umin + THR_STEPS, exact fp32 rescore, first-index tie-break.
// ---------------------------------------------------------------------------
__global__ void scan_kernel(const float* __restrict__ d1,
                            const float* __restrict__ d2,
                            float* __restrict__ out) {
    int warp = (blockIdx.x * blockDim.x + threadIdx.x) >> 5;
    int lane = threadIdx.x & 31;
    if (warp >= NB1) return;
    const int row = warp;
    const uint4* vrow = (const uint4*)(g_vbuf + (size_t)row * NB2);  // 512 uint4

    // ---- threshold from precomputed per-split mins (64 bytes) ----
    uint32_t mn = 0xFFFFFFFFu;
    if (lane < 16)
        mn = ((const uint32_t*)(g_rmin + row * SPLITC * 2))[lane];
    #pragma unroll
    for (int o = 16; o; o >>= 1)
        mn = __vminu4(mn, __shfl_xor_sync(0xffffffffu, mn, o));
    uint32_t umin = min(min(mn & 255u, (mn >> 8) & 255u),
                        min((mn >> 16) & 255u, (mn >> 24) & 255u));
    uint32_t uthr = min(umin + THR_STEPS, 255u);
    const uint32_t thr4 = uthr * 0x01010101u;

    // ---- single sweep: candidates + exact rescore ----
    float4 a4 = ((const float4*)(d1 + (size_t)row * ND))[lane];
    float n1r = g_n1[row];
    float bv = 3.4e38f;
    int   bj = 0x7fffffff;

    for (int it = 0; it < 16; it++) {
        uint4 q = vrow[it * 32 + lane];
        bool f = (__vcmpleu4(q.x, thr4) | __vcmpleu4(q.y, thr4) |
                  __vcmpleu4(q.z, thr4) | __vcmpleu4(q.w, thr4)) != 0u;
        unsigned bm = __ballot_sync(0xffffffffu, f);
        while (bm) {
            int src = __ffs(bm) - 1;
            bm &= bm - 1;
            uint32_t qs[4];
            qs[0] = __shfl_sync(0xffffffffu, q.x, src);
            qs[1] = __shfl_sync(0xffffffffu, q.y, src);
            qs[2] = __shfl_sync(0xffffffffu, q.z, src);
            qs[3] = __shfl_sync(0xffffffffu, q.w, src);
            #pragma unroll
            for (int wj = 0; wj < 4; wj++) {
                uint32_t cm = __vcmpleu4(qs[wj], thr4);
                while (cm) {
                    int bit = __ffs(cm) - 1;
                    cm &= ~(0xFFu << (bit & ~7));
                    int k = wj * 4 + (bit >> 3);
                    int p = (it * 32 + src) * 16 + k;
                    // inverse permutation (intra-128B chunk): byte p -> column j
                    int r7  = p & 127;
                    int w1  = r7 >> 6;
                    int l3  = (r7 >> 4) & 3;
                    int sub = (r7 >> 3) & 1;
                    int n   = (r7 >> 1) & 3;
                    int c   = r7 & 1;
                    int j = (p & ~127) + sub * 64 + w1 * 32 + n * 8 + l3 * 2 + c;
                    float4 b4 = ((const float4*)(d2 + (size_t)j * ND))[lane];
                    float d = a4.x * b4.x + a4.y * b4.y + a4.z * b4.z + a4.w * b4.w;
                    #pragma unroll
                    for (int o = 16; o; o >>= 1)
                        d += __shfl_xor_sync(0xffffffffu, d, o);
                    float v = n1r + g_n2[j] - 2.0f * d;
                    if (v < bv || (v == bv && j < bj)) { bv = v; bj = j; }
                }
            }
        }
    }

    if (lane == 0) {
        out[row] = sqrtf(fmaxf(bv, 0.0f));
        out[NB1 + 2 * row]     = (float)row;
        out[NB1 + 2 * row + 1] = (float)bj;
    }
}

// ---------------------------------------------------------------------------
extern "C" void kernel_launch(void* const* d_in, const int* in_sizes, int n_in,
                              void* d_out, int out_size) {
    const float* d1 = (const float*)d_in[0];
    const float* d2 = (const float*)d_in[1];
    float* out = (float*)d_out;

    cudaFuncSetAttribute(screen_kernel,
                         cudaFuncAttributeMaxDynamicSharedMemorySize, SMEM_BYTES);

    prep_kernel<<<(NB1 + NB2) / 8, 256>>>(d1, d2);
    screen_kernel<<<dim3(NB1 / BM, SPLITC), 256, SMEM_BYTES>>>();
    scan_kernel<<<NB1 / 8, 256>>>(d1, d2, out);
}

// round 16
// speedup vs baseline: 1.2180x; 1.0201x over previous
#include <cuda_runtime.h>
#include <cuda_fp16.h>
#include <math.h>
#include <stdint.h>

// ---------------- problem constants ----------------
#define NB1 8192
#define NB2 8192
#define ND  128

// ---------------- phase A tiling ----------------
#define BM 128
#define BN 64
#define SPLITC 8
#define COLS_PER_CTA (NB2 / SPLITC)          // 1024
#define OUTER (COLS_PER_CTA / (2 * BN))      // 8 iterations x 128 cols

// u8 quantization of screen values: u = clamp(round((v - QLO) / QSTEP))
#define QLO   (-64.0f)
#define QSTEP 1.5f
#define QINV  (1.0f / QSTEP)
#define THR_STEPS 3          // 4.5 decoded margin (need >= 2.06)

// smem map: Ah 32KB | Bh ring 4 x 16KB | n2 4KB
#define SMEM_A 0
#define SMEM_B 32768
#define BSTAGE 16384
#define SMEM_N2 (SMEM_B + 4 * BSTAGE)        // 98304
#define SMEM_BYTES (SMEM_N2 + 4096)          // 102400 (2 CTAs/SM)

#define SW128(o) ((o) ^ (((o) >> 3) & 0x70))

// ---------------- scratch globals ----------------
__device__ __align__(16) float  g_n1[NB1];
__device__ __align__(16) float  g_n2[NB2];
__device__ __align__(16) __half g_Ah[NB1 * ND];
__device__ __align__(16) __half g_Bh[NB2 * ND];
__device__ __align__(16) uint8_t g_vbuf[(size_t)NB1 * NB2];      // 64MB u8 screen values
__device__ __align__(16) uint8_t g_rmin[NB1 * SPLITC * 2];       // per (row, split, colwarp) min

// ---------------- PTX helpers (portable sm_80-level only) ----------------
__device__ __forceinline__ uint32_t smem_u32(const void* p) {
    uint32_t a;
    asm("{ .reg .u64 t; cvta.to.shared.u64 t, %1; cvt.u32.u64 %0, t; }" : "=r"(a) : "l"(p));
    return a;
}
#define CP_ASYNC16(dst, src) \
    asm volatile("cp.async.cg.shared.global [%0], [%1], 16;" :: "r"(dst), "l"(src) : "memory")
#define CP_COMMIT() asm volatile("cp.async.commit_group;" ::: "memory")
#define CP_WAIT0()  asm volatile("cp.async.wait_group 0;" ::: "memory")

#define LDMATRIX_X4(r0, r1, r2, r3, addr) \
    asm volatile("ldmatrix.sync.aligned.m8n8.x4.shared.b16 {%0,%1,%2,%3}, [%4];" \
        : "=r"(r0), "=r"(r1), "=r"(r2), "=r"(r3) : "r"(addr))

#define MMA16816(acc, a, b0v, b1v) \
    asm volatile("mma.sync.aligned.m16n8k16.row.col.f32.f16.f16.f32 " \
        "{%0,%1,%2,%3}, {%4,%5,%6,%7}, {%8,%9}, {%0,%1,%2,%3};" \
        : "+f"((acc)[0]), "+f"((acc)[1]), "+f"((acc)[2]), "+f"((acc)[3]) \
        : "r"((a)[0]), "r"((a)[1]), "r"((a)[2]), "r"((a)[3]), "r"(b0v), "r"(b1v))

__device__ __forceinline__ uint32_t quant4(float v0, float v1, float v2, float v3) {
    int u0 = __float2int_rn((v0 - QLO) * QINV);
    int u1 = __float2int_rn((v1 - QLO) * QINV);
    int u2 = __float2int_rn((v2 - QLO) * QINV);
    int u3 = __float2int_rn((v3 - QLO) * QINV);
    u0 = min(max(u0, 0), 255); u1 = min(max(u1, 0), 255);
    u2 = min(max(u2, 0), 255); u3 = min(max(u3, 0), 255);
    return (uint32_t)u0 | ((uint32_t)u1 << 8) | ((uint32_t)u2 << 16) | ((uint32_t)u3 << 24);
}

// ---------------------------------------------------------------------------
// Kernel 0: fp16 hi conversion + squared norms. One warp per row.
// ---------------------------------------------------------------------------
__global__ void prep_kernel(const float* __restrict__ d1,
                            const float* __restrict__ d2) {
    int warp = (blockIdx.x * blockDim.x + threadIdx.x) >> 5;
    int lane = threadIdx.x & 31;
    if (warp >= NB1 + NB2) return;
    bool isB = (warp >= NB1);
    int row = isB ? warp - NB1 : warp;
    const float* src = (isB ? d2 : d1) + (size_t)row * ND;
    float4 v = ((const float4*)src)[lane];

    float s = v.x * v.x + v.y * v.y + v.z * v.z + v.w * v.w;
    #pragma unroll
    for (int o = 16; o; o >>= 1) s += __shfl_xor_sync(0xffffffffu, s, o);
    if (lane == 0) {
        if (isB) g_n2[row] = s;
        else     g_n1[row] = s;
    }

    __half2 h01 = __halves2half2(__float2half_rn(v.x), __float2half_rn(v.y));
    __half2 h23 = __halves2half2(__float2half_rn(v.z), __float2half_rn(v.w));
    uint2 hp = make_uint2(*(uint32_t*)&h01, *(uint32_t*)&h23);
    ((uint2*)(isB ? g_Bh : g_Ah))[(size_t)row * 32 + lane] = hp;
}

// ---------------------------------------------------------------------------
// smem loaders (SW128-swizzled K-major hi tiles)
// ---------------------------------------------------------------------------
__device__ __forceinline__ void load_a_panel(uint32_t dstbase, int row0, int tid) {
    #pragma unroll
    for (int g = 0; g < 8; g++) {
        int idx = g * 256 + tid;
        int chunk = idx >> 10;
        int rem   = idx & 1023;
        int row   = rem >> 3;
        int gi    = rem & 7;
        const __half* src = g_Ah + (size_t)(row0 + row) * ND + chunk * 64 + gi * 8;
        CP_ASYNC16(dstbase + chunk * 16384 + SW128(row * 128 + gi * 16), src);
    }
}
__device__ __forceinline__ void load_b_stage(uint32_t dstbase, int col0, int tid) {
    #pragma unroll
    for (int g = 0; g < 4; g++) {
        int idx = g * 256 + tid;
        int chunk = idx >> 9;
        int rem   = idx & 511;
        int row   = rem >> 3;
        int gi    = rem & 7;
        const __half* src = g_Bh + (size_t)(col0 + row) * ND + chunk * 64 + gi * 8;
        CP_ASYNC16(dstbase + chunk * 8192 + SW128(row * 128 + gi * 16), src);
    }
}

// ---------------------------------------------------------------------------
// Kernel 1 (screen): hi-only mma.sync GEMM; epilogue quantizes v = n2 - 2*dot
// to u8, stores PERMUTED (one STG.128 per (m,ch)), and keeps a register
// running byte-min per (m,ch) row-slot; quad-reduced min -> g_rmin at the end.
//   byte p (within the 128B iter-chunk) = w1*64 + l3*16 + sub*8 + n*2 + c
//   column j (within the chunk)         = sub*64 + w1*32 + n*8 + l3*2 + c
// ---------------------------------------------------------------------------
__global__ void __launch_bounds__(256, 2)
screen_kernel() {
    extern __shared__ char smem[];
    const uint32_t sbase = smem_u32(smem);
    const int tid  = threadIdx.x;
    const int lane = tid & 31;
    const int warp = tid >> 5;
    const int wrow = (warp >> 1) * 32;
    const int wcol = (warp & 1) * 32;
    const int rowBase = blockIdx.x * BM;
    const int split   = blockIdx.y;
    const int colBase = split * COLS_PER_CTA;

    const int a_rl   = lane & 15;
    const int a_koff = (lane >> 4) * 8;
    const int b_nl   = (lane & 7) + (lane >> 4) * 8;
    const int b_koff = ((lane >> 3) & 1) * 8;

    // ---- prologue: A panel + n2 + stages 0,1 ----
    load_a_panel(sbase + SMEM_A, rowBase, tid);
    CP_ASYNC16(sbase + SMEM_N2 + tid * 16, g_n2 + colBase + tid * 4);  // 4KB n2
    load_b_stage(sbase + SMEM_B + 0 * BSTAGE, colBase + 0 * BN, tid);
    CP_COMMIT();
    load_b_stage(sbase + SMEM_B + 1 * BSTAGE, colBase + 1 * BN, tid);
    CP_COMMIT();

    const float* n2s = (const float*)(smem + SMEM_N2);

    uint32_t rmin[2][2] = {{0xFFFFFFFFu, 0xFFFFFFFFu}, {0xFFFFFFFFu, 0xFFFFFFFFu}};

    for (int it = 0; it < OUTER; it++) {
        CP_WAIT0();
        __syncthreads();

        if (it + 1 < OUTER) {
            load_b_stage(sbase + SMEM_B + (((it + 1) * 2) & 3) * BSTAGE,
                         colBase + (it + 1) * 2 * BN, tid);
            CP_COMMIT();
            load_b_stage(sbase + SMEM_B + (((it + 1) * 2 + 1) & 3) * BSTAGE,
                         colBase + ((it + 1) * 2 + 1) * BN, tid);
            CP_COMMIT();
        }

        const uint32_t abase = sbase + SMEM_A;
        const uint32_t bbase0 = sbase + SMEM_B + ((it * 2) & 3) * BSTAGE;
        const uint32_t bbase1 = sbase + SMEM_B + ((it * 2 + 1) & 3) * BSTAGE;

        float acc[2][2][4][4];     // [m][subtile][npair][c]
        #pragma unroll
        for (int m = 0; m < 2; m++)
            #pragma unroll
            for (int sub = 0; sub < 2; sub++)
                #pragma unroll
                for (int n = 0; n < 4; n++)
                    #pragma unroll
                    for (int c = 0; c < 4; c++) acc[m][sub][n][c] = 0.0f;

        #pragma unroll
        for (int ks = 0; ks < 8; ks++) {
            uint32_t aH[2][4];
            #pragma unroll
            for (int m = 0; m < 2; m++) {
                int row = wrow + m * 16 + a_rl;
                int kb  = ks * 16 + a_koff;
                uint32_t addr = abase + (kb >> 6) * 16384 + row * 128 +
                                (((kb & 63) * 2) ^ ((row & 7) << 4));
                LDMATRIX_X4(aH[m][0], aH[m][1], aH[m][2], aH[m][3], addr);
            }
            #pragma unroll
            for (int sub = 0; sub < 2; sub++) {
                const uint32_t bbase = sub ? bbase1 : bbase0;
                uint32_t bH[2][4];
                #pragma unroll
                for (int pr = 0; pr < 2; pr++) {
                    int nrow = wcol + pr * 16 + b_nl;
                    int kb   = ks * 16 + b_koff;
                    uint32_t addr = bbase + (kb >> 6) * 8192 + nrow * 128 +
                                    (((kb & 63) * 2) ^ ((nrow & 7) << 4));
                    LDMATRIX_X4(bH[pr][0], bH[pr][1], bH[pr][2], bH[pr][3], addr);
                }
                #pragma unroll
                for (int m = 0; m < 2; m++) {
                    MMA16816(acc[m][sub][0], aH[m], bH[0][0], bH[0][1]);
                    MMA16816(acc[m][sub][1], aH[m], bH[0][2], bH[0][3]);
                    MMA16816(acc[m][sub][2], aH[m], bH[1][0], bH[1][1]);
                    MMA16816(acc[m][sub][3], aH[m], bH[1][2], bH[1][3]);
                }
            }
        }

        // ---- epilogue: quantize to u8, running min, one STG.128 per (m,ch) ----
        float n2v[2][8];
        #pragma unroll
        for (int sub = 0; sub < 2; sub++) {
            const int cloc = it * 128 + sub * 64 + wcol;
            #pragma unroll
            for (int n = 0; n < 4; n++) {
                n2v[sub][n * 2]     = n2s[cloc + n * 8 + (lane & 3) * 2];
                n2v[sub][n * 2 + 1] = n2s[cloc + n * 8 + (lane & 3) * 2 + 1];
            }
        }
        #pragma unroll
        for (int m = 0; m < 2; m++) {
            #pragma unroll
            for (int ch = 0; ch < 2; ch++) {
                uint32_t w[4];
                #pragma unroll
                for (int sub = 0; sub < 2; sub++) {
                    #pragma unroll
                    for (int np = 0; np < 2; np++) {
                        int n0 = np * 2, n1 = np * 2 + 1;
                        w[sub * 2 + np] = quant4(
                            n2v[sub][n0 * 2]     - 2.0f * acc[m][sub][n0][ch * 2],
                            n2v[sub][n0 * 2 + 1] - 2.0f * acc[m][sub][n0][ch * 2 + 1],
                            n2v[sub][n1 * 2]     - 2.0f * acc[m][sub][n1][ch * 2],
                            n2v[sub][n1 * 2 + 1] - 2.0f * acc[m][sub][n1][ch * 2 + 1]);
                    }
                }
                rmin[m][ch] = __vminu4(rmin[m][ch],
                              __vminu4(__vminu4(w[0], w[1]), __vminu4(w[2], w[3])));
                int grow = rowBase + wrow + m * 16 + ch * 8 + (lane >> 2);
                size_t p = (size_t)grow * NB2 + colBase + it * 128 +
                           (warp & 1) * 64 + (lane & 3) * 16;
                *(uint4*)(g_vbuf + p) = make_uint4(w[0], w[1], w[2], w[3]);
            }
        }
    }

    // ---- final: quad-reduce running mins, one byte store per row-slot ----
    #pragma unroll
    for (int m = 0; m < 2; m++)
        #pragma unroll
        for (int ch = 0; ch < 2; ch++) {
            uint32_t v = rmin[m][ch];
            v = __vminu4(v, __shfl_xor_sync(0xffffffffu, v, 1));
            v = __vminu4(v, __shfl_xor_sync(0xffffffffu, v, 2));
            uint32_t b = min(min(v & 255u, (v >> 8) & 255u),
                             min((v >> 16) & 255u, (v >> 24) & 255u));
            if ((lane & 3) == 0) {
                int grow = rowBase + wrow + m * 16 + ch * 8 + (lane >> 2);
                g_rmin[(grow * SPLITC + split) * 2 + (warp & 1)] = (uint8_t)b;
            }
        }
}

// ---------------------------------------------------------------------------
// Kernel 2 (scan): warp per row. Threshold from g_rmin (16 bytes), one sweep:
// candidates u <= umin + THR_STEPS, exact fp32 rescore, first-index tie-break.
// ---------------------------------------------------------------------------
__global__ void scan_kernel(const float* __restrict__ d1,
                            const float* __restrict__ d2,
                            float* __restrict__ out) {
    int warp = (blockIdx.x * blockDim.x + threadIdx.x) >> 5;
    int lane = threadIdx.x & 31;
    if (warp >= NB1) return;
    const int row = warp;
    const uint4* vrow = (const uint4*)(g_vbuf + (size_t)row * NB2);  // 512 uint4

    // ---- threshold from precomputed per-split mins (16 bytes) ----
    uint32_t mn = 0xFFFFFFFFu;
    if (lane < 4)
        mn = ((const uint32_t*)(g_rmin + row * SPLITC * 2))[lane];
    #pragma unroll
    for (int o = 2; o; o >>= 1)
        mn = __vminu4(mn, __shfl_xor_sync(0xffffffffu, mn, o));
    mn = __shfl_sync(0xffffffffu, mn, 0);
    uint32_t umin = min(min(mn & 255u, (mn >> 8) & 255u),
                        min((mn >> 16) & 255u, (mn >> 24) & 255u));
    uint32_t uthr = min(umin + THR_STEPS, 255u);
    const uint32_t thr4 = uthr * 0x01010101u;

    // ---- single sweep: candidates + exact rescore ----
    float4 a4 = ((const float4*)(d1 + (size_t)row * ND))[lane];
    float n1r = g_n1[row];
    float bv = 3.4e38f;
    int   bj = 0x7fffffff;

    for (int it = 0; it < 16; it++) {
        uint4 q = vrow[it * 32 + lane];
        bool f = (__vcmpleu4(q.x, thr4) | __vcmpleu4(q.y, thr4) |
                  __vcmpleu4(q.z, thr4) | __vcmpleu4(q.w, thr4)) != 0u;
        unsigned bm = __ballot_sync(0xffffffffu, f);
        while (bm) {
            int src = __ffs(bm) - 1;
            bm &= bm - 1;
            uint32_t qs[4];
            qs[0] = __shfl_sync(0xffffffffu, q.x, src);
            qs[1] = __shfl_sync(0xffffffffu, q.y, src);
            qs[2] = __shfl_sync(0xffffffffu, q.z, src);
            qs[3] = __shfl_sync(0xffffffffu, q.w, src);
            #pragma unroll
            for (int wj = 0; wj < 4; wj++) {
                uint32_t cm = __vcmpleu4(qs[wj], thr4);
                while (cm) {
                    int bit = __ffs(cm) - 1;
                    cm &= ~(0xFFu << (bit & ~7));
                    int k = wj * 4 + (bit >> 3);
                    int p = (it * 32 + src) * 16 + k;
                    // inverse permutation (intra-128B chunk): byte p -> column j
                    int r7  = p & 127;
                    int w1  = r7 >> 6;
                    int l3  = (r7 >> 4) & 3;
                    int sub = (r7 >> 3) & 1;
                    int n   = (r7 >> 1) & 3;
                    int c   = r7 & 1;
                    int j = (p & ~127) + sub * 64 + w1 * 32 + n * 8 + l3 * 2 + c;
                    float4 b4 = ((const float4*)(d2 + (size_t)j * ND))[lane];
                    float d = a4.x * b4.x + a4.y * b4.y + a4.z * b4.z + a4.w * b4.w;
                    #pragma unroll
                    for (int o = 16; o; o >>= 1)
                        d += __shfl_xor_sync(0xffffffffu, d, o);
                    float v = n1r + g_n2[j] - 2.0f * d;
                    if (v < bv || (v == bv && j < bj)) { bv = v; bj = j; }
                }
            }
        }
    }

    if (lane == 0) {
        out[row] = sqrtf(fmaxf(bv, 0.0f));
        out[NB1 + 2 * row]     = (float)row;
        out[NB1 + 2 * row + 1] = (float)bj;
    }
}

// ---------------------------------------------------------------------------
extern "C" void kernel_launch(void* const* d_in, const int* in_sizes, int n_in,
                              void* d_out, int out_size) {
    const float* d1 = (const float*)d_in[0];
    const float* d2 = (const float*)d_in[1];
    float* out = (float*)d_out;

    cudaFuncSetAttribute(screen_kernel,
                         cudaFuncAttributeMaxDynamicSharedMemorySize, SMEM_BYTES);

    prep_kernel<<<(NB1 + NB2) / 8, 256>>>(d1, d2);
    screen_kernel<<<dim3(NB1 / BM, SPLITC), 256, SMEM_BYTES>>>();
    scan_kernel<<<NB1 / 8, 256>>>(d1, d2, out);
}

// round 17
// speedup vs baseline: 1.3471x; 1.1060x over previous
#include <cuda_runtime.h>
#include <cuda_fp16.h>
#include <math.h>
#include <stdint.h>

// ---------------- problem constants ----------------
#define NB1 8192
#define NB2 8192
#define ND  128

// ---------------- phase A tiling ----------------
#define BM 128
#define BN 64
#define SPLITC 16
#define COLS_PER_CTA (NB2 / SPLITC)          // 512
#define OUTER (COLS_PER_CTA / (2 * BN))      // 4 iterations x 128 cols

// u8 quantization of screen values: u = clamp(round((v - QLO) / QSTEP))
#define QLO   (-64.0f)
#define QSTEP 1.5f
#define QINV  (1.0f / QSTEP)
#define THR_STEPS 3          // 4.5 decoded margin (need >= 2.06)

// smem map: Ah 32KB | Bh ring 4 x 16KB | n2 2KB
#define SMEM_A 0
#define SMEM_B 32768
#define BSTAGE 16384
#define SMEM_N2 (SMEM_B + 4 * BSTAGE)        // 98304
#define SMEM_BYTES (SMEM_N2 + 2048)          // 100352 (2 CTAs/SM)

#define SW128(o) ((o) ^ (((o) >> 3) & 0x70))

// ---------------- scratch globals ----------------
__device__ __align__(16) float  g_n1[NB1];
__device__ __align__(16) float  g_n2[NB2];
__device__ __align__(16) __half g_Ah[NB1 * ND];
__device__ __align__(16) __half g_Bh[NB2 * ND];
__device__ __align__(16) uint8_t g_vbuf[(size_t)NB1 * NB2];      // 64MB u8 screen values
__device__ __align__(16) uint8_t g_rmin[NB1 * SPLITC * 2];       // per (row, split, colwarp) min

// ---------------- PTX helpers (portable sm_80-level only) ----------------
__device__ __forceinline__ uint32_t smem_u32(const void* p) {
    uint32_t a;
    asm("{ .reg .u64 t; cvta.to.shared.u64 t, %1; cvt.u32.u64 %0, t; }" : "=r"(a) : "l"(p));
    return a;
}
#define CP_ASYNC16(dst, src) \
    asm volatile("cp.async.cg.shared.global [%0], [%1], 16;" :: "r"(dst), "l"(src) : "memory")
#define CP_COMMIT() asm volatile("cp.async.commit_group;" ::: "memory")
#define CP_WAIT0()  asm volatile("cp.async.wait_group 0;" ::: "memory")

#define LDMATRIX_X4(r0, r1, r2, r3, addr) \
    asm volatile("ldmatrix.sync.aligned.m8n8.x4.shared.b16 {%0,%1,%2,%3}, [%4];" \
        : "=r"(r0), "=r"(r1), "=r"(r2), "=r"(r3) : "r"(addr))

#define MMA16816(acc, a, b0v, b1v) \
    asm volatile("mma.sync.aligned.m16n8k16.row.col.f32.f16.f16.f32 " \
        "{%0,%1,%2,%3}, {%4,%5,%6,%7}, {%8,%9}, {%0,%1,%2,%3};" \
        : "+f"((acc)[0]), "+f"((acc)[1]), "+f"((acc)[2]), "+f"((acc)[3]) \
        : "r"((a)[0]), "r"((a)[1]), "r"((a)[2]), "r"((a)[3]), "r"(b0v), "r"(b1v))

__device__ __forceinline__ uint32_t quant4(float v0, float v1, float v2, float v3) {
    int u0 = __float2int_rn((v0 - QLO) * QINV);
    int u1 = __float2int_rn((v1 - QLO) * QINV);
    int u2 = __float2int_rn((v2 - QLO) * QINV);
    int u3 = __float2int_rn((v3 - QLO) * QINV);
    u0 = min(max(u0, 0), 255); u1 = min(max(u1, 0), 255);
    u2 = min(max(u2, 0), 255); u3 = min(max(u3, 0), 255);
    return (uint32_t)u0 | ((uint32_t)u1 << 8) | ((uint32_t)u2 << 16) | ((uint32_t)u3 << 24);
}

// ---------------------------------------------------------------------------
// Kernel 0: fp16 hi conversion + squared norms. One warp per row.
// ---------------------------------------------------------------------------
__global__ void prep_kernel(const float* __restrict__ d1,
                            const float* __restrict__ d2) {
    int warp = (blockIdx.x * blockDim.x + threadIdx.x) >> 5;
    int lane = threadIdx.x & 31;
    if (warp >= NB1 + NB2) return;
    bool isB = (warp >= NB1);
    int row = isB ? warp - NB1 : warp;
    const float* src = (isB ? d2 : d1) + (size_t)row * ND;
    float4 v = ((const float4*)src)[lane];

    float s = v.x * v.x + v.y * v.y + v.z * v.z + v.w * v.w;
    #pragma unroll
    for (int o = 16; o; o >>= 1) s += __shfl_xor_sync(0xffffffffu, s, o);
    if (lane == 0) {
        if (isB) g_n2[row] = s;
        else     g_n1[row] = s;
    }

    __half2 h01 = __halves2half2(__float2half_rn(v.x), __float2half_rn(v.y));
    __half2 h23 = __halves2half2(__float2half_rn(v.z), __float2half_rn(v.w));
    uint2 hp = make_uint2(*(uint32_t*)&h01, *(uint32_t*)&h23);
    ((uint2*)(isB ? g_Bh : g_Ah))[(size_t)row * 32 + lane] = hp;
}

// ---------------------------------------------------------------------------
// smem loaders (SW128-swizzled K-major hi tiles)
// ---------------------------------------------------------------------------
__device__ __forceinline__ void load_a_panel(uint32_t dstbase, int row0, int tid) {
    #pragma unroll
    for (int g = 0; g < 8; g++) {
        int idx = g * 256 + tid;
        int chunk = idx >> 10;
        int rem   = idx & 1023;
        int row   = rem >> 3;
        int gi    = rem & 7;
        const __half* src = g_Ah + (size_t)(row0 + row) * ND + chunk * 64 + gi * 8;
        CP_ASYNC16(dstbase + chunk * 16384 + SW128(row * 128 + gi * 16), src);
    }
}
__device__ __forceinline__ void load_b_stage(uint32_t dstbase, int col0, int tid) {
    #pragma unroll
    for (int g = 0; g < 4; g++) {
        int idx = g * 256 + tid;
        int chunk = idx >> 9;
        int rem   = idx & 511;
        int row   = rem >> 3;
        int gi    = rem & 7;
        const __half* src = g_Bh + (size_t)(col0 + row) * ND + chunk * 64 + gi * 8;
        CP_ASYNC16(dstbase + chunk * 8192 + SW128(row * 128 + gi * 16), src);
    }
}

// ---------------------------------------------------------------------------
// Kernel 1 (screen): hi-only mma.sync GEMM; epilogue quantizes v = n2 - 2*dot
// to u8, stores PERMUTED (one STG.128 per (m,ch)), and keeps a register
// running byte-min per (m,ch) row-slot; quad-reduced min -> g_rmin at the end.
//   byte p (within the 128B iter-chunk) = w1*64 + l3*16 + sub*8 + n*2 + c
//   column j (within the chunk)         = sub*64 + w1*32 + n*8 + l3*2 + c
// ---------------------------------------------------------------------------
__global__ void __launch_bounds__(256, 2)
screen_kernel() {
    extern __shared__ char smem[];
    const uint32_t sbase = smem_u32(smem);
    const int tid  = threadIdx.x;
    const int lane = tid & 31;
    const int warp = tid >> 5;
    const int wrow = (warp >> 1) * 32;
    const int wcol = (warp & 1) * 32;
    const int rowBase = blockIdx.x * BM;
    const int split   = blockIdx.y;
    const int colBase = split * COLS_PER_CTA;

    const int a_rl   = lane & 15;
    const int a_koff = (lane >> 4) * 8;
    const int b_nl   = (lane & 7) + (lane >> 4) * 8;
    const int b_koff = ((lane >> 3) & 1) * 8;

    // ---- prologue: A panel + n2 + stages 0,1 ----
    load_a_panel(sbase + SMEM_A, rowBase, tid);
    if (tid < 128)
        CP_ASYNC16(sbase + SMEM_N2 + tid * 16, g_n2 + colBase + tid * 4);
    load_b_stage(sbase + SMEM_B + 0 * BSTAGE, colBase + 0 * BN, tid);
    CP_COMMIT();
    load_b_stage(sbase + SMEM_B + 1 * BSTAGE, colBase + 1 * BN, tid);
    CP_COMMIT();

    const float* n2s = (const float*)(smem + SMEM_N2);

    uint32_t rmin[2][2] = {{0xFFFFFFFFu, 0xFFFFFFFFu}, {0xFFFFFFFFu, 0xFFFFFFFFu}};

    for (int it = 0; it < OUTER; it++) {
        CP_WAIT0();
        __syncthreads();

        if (it + 1 < OUTER) {
            load_b_stage(sbase + SMEM_B + (((it + 1) * 2) & 3) * BSTAGE,
                         colBase + (it + 1) * 2 * BN, tid);
            CP_COMMIT();
            load_b_stage(sbase + SMEM_B + (((it + 1) * 2 + 1) & 3) * BSTAGE,
                         colBase + ((it + 1) * 2 + 1) * BN, tid);
            CP_COMMIT();
        }

        const uint32_t abase = sbase + SMEM_A;
        const uint32_t bbase0 = sbase + SMEM_B + ((it * 2) & 3) * BSTAGE;
        const uint32_t bbase1 = sbase + SMEM_B + ((it * 2 + 1) & 3) * BSTAGE;

        float acc[2][2][4][4];     // [m][subtile][npair][c]
        #pragma unroll
        for (int m = 0; m < 2; m++)
            #pragma unroll
            for (int sub = 0; sub < 2; sub++)
                #pragma unroll
                for (int n = 0; n < 4; n++)
                    #pragma unroll
                    for (int c = 0; c < 4; c++) acc[m][sub][n][c] = 0.0f;

        #pragma unroll
        for (int ks = 0; ks < 8; ks++) {
            uint32_t aH[2][4];
            #pragma unroll
            for (int m = 0; m < 2; m++) {
                int row = wrow + m * 16 + a_rl;
                int kb  = ks * 16 + a_koff;
                uint32_t addr = abase + (kb >> 6) * 16384 + row * 128 +
                                (((kb & 63) * 2) ^ ((row & 7) << 4));
                LDMATRIX_X4(aH[m][0], aH[m][1], aH[m][2], aH[m][3], addr);
            }
            #pragma unroll
            for (int sub = 0; sub < 2; sub++) {
                const uint32_t bbase = sub ? bbase1 : bbase0;
                uint32_t bH[2][4];
                #pragma unroll
                for (int pr = 0; pr < 2; pr++) {
                    int nrow = wcol + pr * 16 + b_nl;
                    int kb   = ks * 16 + b_koff;
                    uint32_t addr = bbase + (kb >> 6) * 8192 + nrow * 128 +
                                    (((kb & 63) * 2) ^ ((nrow & 7) << 4));
                    LDMATRIX_X4(bH[pr][0], bH[pr][1], bH[pr][2], bH[pr][3], addr);
                }
                #pragma unroll
                for (int m = 0; m < 2; m++) {
                    MMA16816(acc[m][sub][0], aH[m], bH[0][0], bH[0][1]);
                    MMA16816(acc[m][sub][1], aH[m], bH[0][2], bH[0][3]);
                    MMA16816(acc[m][sub][2], aH[m], bH[1][0], bH[1][1]);
                    MMA16816(acc[m][sub][3], aH[m], bH[1][2], bH[1][3]);
                }
            }
        }

        // ---- epilogue: quantize to u8, running min, one STG.128 per (m,ch) ----
        float n2v[2][8];
        #pragma unroll
        for (int sub = 0; sub < 2; sub++) {
            const int cloc = it * 128 + sub * 64 + wcol;
            #pragma unroll
            for (int n = 0; n < 4; n++) {
                n2v[sub][n * 2]     = n2s[cloc + n * 8 + (lane & 3) * 2];
                n2v[sub][n * 2 + 1] = n2s[cloc + n * 8 + (lane & 3) * 2 + 1];
            }
        }
        #pragma unroll
        for (int m = 0; m < 2; m++) {
            #pragma unroll
            for (int ch = 0; ch < 2; ch++) {
                uint32_t w[4];
                #pragma unroll
                for (int sub = 0; sub < 2; sub++) {
                    #pragma unroll
                    for (int np = 0; np < 2; np++) {
                        int n0 = np * 2, n1 = np * 2 + 1;
                        w[sub * 2 + np] = quant4(
                            n2v[sub][n0 * 2]     - 2.0f * acc[m][sub][n0][ch * 2],
                            n2v[sub][n0 * 2 + 1] - 2.0f * acc[m][sub][n0][ch * 2 + 1],
                            n2v[sub][n1 * 2]     - 2.0f * acc[m][sub][n1][ch * 2],
                            n2v[sub][n1 * 2 + 1] - 2.0f * acc[m][sub][n1][ch * 2 + 1]);
                    }
                }
                rmin[m][ch] = __vminu4(rmin[m][ch],
                              __vminu4(__vminu4(w[0], w[1]), __vminu4(w[2], w[3])));
                int grow = rowBase + wrow + m * 16 + ch * 8 + (lane >> 2);
                size_t p = (size_t)grow * NB2 + split * 512 + it * 128 +
                           (warp & 1) * 64 + (lane & 3) * 16;
                *(uint4*)(g_vbuf + p) = make_uint4(w[0], w[1], w[2], w[3]);
            }
        }
    }

    // ---- final: quad-reduce running mins, one byte store per row-slot ----
    #pragma unroll
    for (int m = 0; m < 2; m++)
        #pragma unroll
        for (int ch = 0; ch < 2; ch++) {
            uint32_t v = rmin[m][ch];
            v = __vminu4(v, __shfl_xor_sync(0xffffffffu, v, 1));
            v = __vminu4(v, __shfl_xor_sync(0xffffffffu, v, 2));
            uint32_t b = min(min(v & 255u, (v >> 8) & 255u),
                             min((v >> 16) & 255u, (v >> 24) & 255u));
            if ((lane & 3) == 0) {
                int grow = rowBase + wrow + m * 16 + ch * 8 + (lane >> 2);
                g_rmin[(grow * SPLITC + split) * 2 + (warp & 1)] = (uint8_t)b;
            }
        }
}

// ---------------------------------------------------------------------------
// Kernel 2 (scan): warp per row. Threshold from g_rmin (32 bytes), one sweep
// with 4-deep load batching (MLP=4) over the row's 8192 u8 values:
// candidates u <= umin + THR_STEPS, exact fp32 rescore, first-index tie-break.
// ---------------------------------------------------------------------------
__global__ void scan_kernel(const float* __restrict__ d1,
                            const float* __restrict__ d2,
                            float* __restrict__ out) {
    int warp = (blockIdx.x * blockDim.x + threadIdx.x) >> 5;
    int lane = threadIdx.x & 31;
    if (warp >= NB1) return;
    const int row = warp;
    const uint4* vrow = (const uint4*)(g_vbuf + (size_t)row * NB2);  // 512 uint4

    // ---- threshold from precomputed per-split mins (32 bytes) ----
    uint32_t mn = 0xFFFFFFFFu;
    if (lane < 8)
        mn = ((const uint32_t*)(g_rmin + row * SPLITC * 2))[lane];
    #pragma unroll
    for (int o = 4; o; o >>= 1)
        mn = __vminu4(mn, __shfl_xor_sync(0xffffffffu, mn, o));
    mn = __shfl_sync(0xffffffffu, mn, 0);
    uint32_t umin = min(min(mn & 255u, (mn >> 8) & 255u),
                        min((mn >> 16) & 255u, (mn >> 24) & 255u));
    uint32_t uthr = min(umin + THR_STEPS, 255u);
    const uint32_t thr4 = uthr * 0x01010101u;

    // ---- single sweep, 4-deep batched loads: candidates + exact rescore ----
    float4 a4 = ((const float4*)(d1 + (size_t)row * ND))[lane];
    float n1r = g_n1[row];
    float bv = 3.4e38f;
    int   bj = 0x7fffffff;

    for (int it0 = 0; it0 < 16; it0 += 4) {
        uint4 qb[4];
        #pragma unroll
        for (int i = 0; i < 4; i++)
            qb[i] = vrow[(it0 + i) * 32 + lane];        // 4 independent LDG.128

        #pragma unroll
        for (int i = 0; i < 4; i++) {
            const int it = it0 + i;
            uint4 q = qb[i];
            bool f = (__vcmpleu4(q.x, thr4) | __vcmpleu4(q.y, thr4) |
                      __vcmpleu4(q.z, thr4) | __vcmpleu4(q.w, thr4)) != 0u;
            unsigned bm = __ballot_sync(0xffffffffu, f);
            while (bm) {
                int src = __ffs(bm) - 1;
                bm &= bm - 1;
                uint32_t qs[4];
                qs[0] = __shfl_sync(0xffffffffu, q.x, src);
                qs[1] = __shfl_sync(0xffffffffu, q.y, src);
                qs[2] = __shfl_sync(0xffffffffu, q.z, src);
                qs[3] = __shfl_sync(0xffffffffu, q.w, src);
                #pragma unroll
                for (int wj = 0; wj < 4; wj++) {
                    uint32_t cm = __vcmpleu4(qs[wj], thr4);
                    while (cm) {
                        int bit = __ffs(cm) - 1;
                        cm &= ~(0xFFu << (bit & ~7));
                        int k = wj * 4 + (bit >> 3);
                        int p = (it * 32 + src) * 16 + k;
                        // inverse permutation (intra-128B chunk): byte p -> col j
                        int r7  = p & 127;
                        int w1  = r7 >> 6;
                        int l3  = (r7 >> 4) & 3;
                        int sub = (r7 >> 3) & 1;
                        int n   = (r7 >> 1) & 3;
                        int c   = r7 & 1;
                        int j = (p & ~127) + sub * 64 + w1 * 32 + n * 8 + l3 * 2 + c;
                        float4 b4 = ((const float4*)(d2 + (size_t)j * ND))[lane];
                        float d = a4.x * b4.x + a4.y * b4.y + a4.z * b4.z + a4.w * b4.w;
                        #pragma unroll
                        for (int o = 16; o; o >>= 1)
                            d += __shfl_xor_sync(0xffffffffu, d, o);
                        float v = n1r + g_n2[j] - 2.0f * d;
                        if (v < bv || (v == bv && j < bj)) { bv = v; bj = j; }
                    }
                }
            }
        }
    }

    if (lane == 0) {
        out[row] = sqrtf(fmaxf(bv, 0.0f));
        out[NB1 + 2 * row]     = (float)row;
        out[NB1 + 2 * row + 1] = (float)bj;
    }
}

// ---------------------------------------------------------------------------
extern "C" void kernel_launch(void* const* d_in, const int* in_sizes, int n_in,
                              void* d_out, int out_size) {
    const float* d1 = (const float*)d_in[0];
    const float* d2 = (const float*)d_in[1];
    float* out = (float*)d_out;

    cudaFuncSetAttribute(screen_kernel,
                         cudaFuncAttributeMaxDynamicSharedMemorySize, SMEM_BYTES);

    prep_kernel<<<(NB1 + NB2) / 8, 256>>>(d1, d2);
    screen_kernel<<<dim3(NB1 / BM, SPLITC), 256, SMEM_BYTES>>>();
    scan_kernel<<<NB1 / 8, 256>>>(d1, d2, out);
}